// round 8
// baseline (speedup 1.0000x reference)
#include <cuda_runtime.h>
#include <math.h>

#define LDQ 512
#define LSK 2048
#define CS  384
#define NH  12

typedef unsigned long long u64;

// ---------------- scratch ----------------
__device__ float g_q[LDQ*192];
__device__ float g_qp_raw[LDQ*144];
__device__ float g_kv[LSK*384];
__device__ float g_kvp_raw[LSK*432];
__device__ float g_qaug[NH*LDQ*32];
__device__ float g_kaug[NH*LSK*32];
__device__ float g_pv[NH*LSK*48];                  // padded 40 -> 48
__device__ float g_opart[(size_t)8*NH*LDQ*48];     // AV partials, stride 48
__device__ float g_cat[LDQ*576];

// ---------------- packed f32x2 FMA (Blackwell FFMA2) ----------------
#define FMA2(d, a, b) asm("fma.rn.f32x2 %0, %1, %2, %0;" : "+l"(d) : "l"(a), "l"(b))
__device__ __forceinline__ float2 unpack2(u64 v) {
    float2 f; asm("mov.b64 {%0,%1}, %2;" : "=f"(f.x), "=f"(f.y) : "l"(v)); return f;
}
__device__ __forceinline__ u64 lds_u64(const float* p) {
    return *(const u64*)p;
}

// ---------------- fast exp on the FMA pipe ----------------
__device__ __forceinline__ float fast_exp(float x)
{
    x = fmaxf(x, -87.0f);
    float y  = x * 1.4426950408889634f;
    float t  = y + 12582912.0f;
    int   n  = __float_as_int(t) - 0x4B400000;
    float yi = t - 12582912.0f;
    float f  = y - yi;
    float p = 1.5403530e-4f;
    p = fmaf(p, f, 1.3333558e-3f);
    p = fmaf(p, f, 9.6181291e-3f);
    p = fmaf(p, f, 5.5504109e-2f);
    p = fmaf(p, f, 2.4022651e-1f);
    p = fmaf(p, f, 6.9314718e-1f);
    p = fmaf(p, f, 1.0f);
    return __int_as_float(__float_as_int(p) + (n << 23));
}

// ---------------- 128x64 tile GEMM, 128 threads, 8x8 microtile, FFMA2 ----------------
__device__ __forceinline__ void gemm_128x64_f2(
    const float* __restrict__ A, const float* __restrict__ B, float* __restrict__ C,
    int M, int N, int K)
{
    __shared__ float As2[16][288];   // duplicated pairs: col = 2m + 2*(m>>3)
    __shared__ float Bs[16][64];
    const int t  = threadIdx.x;
    const int tx = t & 7;
    const int ty = t >> 3;
    const int m0 = blockIdx.y * 128;
    const int n0 = blockIdx.x * 64;
    u64 acc[8][4] = {};

    for (int kt = 0; kt < K; kt += 16) {
#pragma unroll
        for (int u = 0; u < 16; u++) {
            int idx = t + 128*u; int m = idx >> 4, k = idx & 15;
            float v = A[(m0 + m)*K + kt + k];
            int col = 2*m + 2*(m >> 3);
            As2[k][col] = v; As2[k][col+1] = v;
        }
#pragma unroll
        for (int u = 0; u < 8; u++) {
            int idx = t + 128*u; int k = idx >> 6, n = idx & 63;
            int gn = n0 + n;
            Bs[k][n] = (gn < N) ? B[(kt + k)*N + gn] : 0.f;
        }
        __syncthreads();
#pragma unroll
        for (int kk = 0; kk < 16; kk++) {
            u64 a0[8], b0[4];
#pragma unroll
            for (int i = 0; i < 8; i++) a0[i] = lds_u64(&As2[kk][18*ty + 2*i]);
#pragma unroll
            for (int j = 0; j < 4; j++) b0[j] = lds_u64(&Bs[kk][tx*8 + 2*j]);
#pragma unroll
            for (int i = 0; i < 8; i++)
#pragma unroll
                for (int j = 0; j < 4; j++)
                    FMA2(acc[i][j], a0[i], b0[j]);
        }
        __syncthreads();
    }
#pragma unroll
    for (int i = 0; i < 8; i++) {
        int gm = m0 + ty*8 + i;
#pragma unroll
        for (int j = 0; j < 4; j++) {
            float2 v = unpack2(acc[i][j]);
            int gn = n0 + tx*8 + 2*j;
            if (gn     < N) C[gm*N + gn]     = v.x;
            if (gn + 1 < N) C[gm*N + gn + 1] = v.y;
        }
    }
}

__global__ __launch_bounds__(128) void proj_all(
    const float* __restrict__ s_dst, const float* __restrict__ s_src,
    const float* __restrict__ Wq, const float* __restrict__ Wqp,
    const float* __restrict__ Wkv, const float* __restrict__ Wkvp)
{
    const float* A; const float* B; float* C; int M, N;
    switch (blockIdx.z) {
        case 0:  A = s_dst; B = Wq;   C = g_q;       M = LDQ; N = 192; break;
        case 1:  A = s_dst; B = Wqp;  C = g_qp_raw;  M = LDQ; N = 144; break;
        case 2:  A = s_src; B = Wkv;  C = g_kv;      M = LSK; N = 384; break;
        default: A = s_src; B = Wkvp; C = g_kvp_raw; M = LSK; N = 432; break;
    }
    if ((int)blockIdx.x*64 >= N || (int)blockIdx.y*128 >= M) return;
    gemm_128x64_f2(A, B, C, M, N, CS);
}

// ---------------- out GEMM: 32x64 tile, 128 threads, 2x8 microtile, FFMA2 ----------------
__global__ __launch_bounds__(128) void out_gemm(
    const float* __restrict__ Wout, const float* __restrict__ bout, float* __restrict__ s_upd)
{
    __shared__ float As2[16][64];    // 32 rows duplicated
    __shared__ float Bs[16][64];
    const int t  = threadIdx.x;
    const int tx = t & 7;
    const int ty = t >> 3;
    const int m0 = blockIdx.y * 32;
    const int n0 = blockIdx.x * 64;
    u64 acc[2][4] = {};

    for (int kt = 0; kt < 576; kt += 16) {
#pragma unroll
        for (int u = 0; u < 4; u++) {
            int idx = t + 128*u; int m = idx >> 4, k = idx & 15;
            float v = g_cat[(m0 + m)*576 + kt + k];
            As2[k][2*m] = v; As2[k][2*m+1] = v;
        }
#pragma unroll
        for (int u = 0; u < 8; u++) {
            int idx = t + 128*u; int k = idx >> 6, n = idx & 63;
            Bs[k][n] = Wout[(kt + k)*384 + n0 + n];
        }
        __syncthreads();
#pragma unroll
        for (int kk = 0; kk < 16; kk++) {
            u64 a0[2], b0[4];
#pragma unroll
            for (int i = 0; i < 2; i++) a0[i] = lds_u64(&As2[kk][4*ty + 2*i]);
#pragma unroll
            for (int j = 0; j < 4; j++) b0[j] = lds_u64(&Bs[kk][tx*8 + 2*j]);
#pragma unroll
            for (int i = 0; i < 2; i++)
#pragma unroll
                for (int j = 0; j < 4; j++)
                    FMA2(acc[i][j], a0[i], b0[j]);
        }
        __syncthreads();
    }
#pragma unroll
    for (int i = 0; i < 2; i++) {
        int gm = m0 + ty*2 + i;
#pragma unroll
        for (int j = 0; j < 4; j++) {
            float2 v = unpack2(acc[i][j]);
            int gn = n0 + tx*8 + 2*j;
            s_upd[gm*384 + gn]     = v.x + bout[gn];
            s_upd[gm*384 + gn + 1] = v.y + bout[gn + 1];
        }
    }
}

// ---------------- augmentation ----------------
__global__ void augq_kernel(const float* __restrict__ R_dst, const float* __restrict__ t_dst,
                            const float* __restrict__ head_w)
{
    int idx = blockIdx.x*256 + threadIdx.x;
    if (idx >= LDQ*NH) return;
    int i = idx / NH, h = idx - (idx/NH)*NH;
    float hw = log1pf(__expf(head_w[h])) * (1.0f/6.0f);
    const float qksc = 0.17677669529663689f;
    float* outp = &g_qaug[(h*LDQ + i)*32];
#pragma unroll
    for (int c = 0; c < 16; c++) outp[c] = g_q[i*192 + h*16 + c] * qksc;
    const float* R = R_dst + i*9; const float* tv = t_dst + i*3;
    float s2 = 0.f;
#pragma unroll
    for (int p = 0; p < 4; p++) {
        float l0 = g_qp_raw[i*144 +       h*4 + p];
        float l1 = g_qp_raw[i*144 + 48  + h*4 + p];
        float l2 = g_qp_raw[i*144 + 96  + h*4 + p];
        float gx = R[0]*l0 + R[1]*l1 + R[2]*l2 + tv[0];
        float gy = R[3]*l0 + R[4]*l1 + R[5]*l2 + tv[1];
        float gz = R[6]*l0 + R[7]*l1 + R[8]*l2 + tv[2];
        outp[16 + p*3 + 0] = hw*gx;
        outp[16 + p*3 + 1] = hw*gy;
        outp[16 + p*3 + 2] = hw*gz;
        s2 = fmaf(gx, gx, fmaf(gy, gy, fmaf(gz, gz, s2)));
    }
    outp[28] = -0.5f*hw*s2; outp[29] = 1.f; outp[30] = 0.f; outp[31] = 0.f;
}

__global__ void augk_kernel(const float* __restrict__ R_src, const float* __restrict__ t_src,
                            const float* __restrict__ head_w)
{
    int idx = blockIdx.x*256 + threadIdx.x;
    if (idx >= LSK*NH) return;
    int j = idx / NH, h = idx - (idx/NH)*NH;
    float hw = log1pf(__expf(head_w[h])) * (1.0f/6.0f);
    float* kout = &g_kaug[(h*LSK + j)*32];
#pragma unroll
    for (int c = 0; c < 16; c++) kout[c] = g_kv[j*384 + h*32 + c];
    const float* R = R_src + j*9; const float* tv = t_src + j*3;
    float s2 = 0.f;
#pragma unroll
    for (int pp = 0; pp < 4; pp++) {
        float l0 = g_kvp_raw[j*432 +        h*12 + pp];
        float l1 = g_kvp_raw[j*432 + 144 +  h*12 + pp];
        float l2 = g_kvp_raw[j*432 + 288 +  h*12 + pp];
        float gx = R[0]*l0 + R[1]*l1 + R[2]*l2 + tv[0];
        float gy = R[3]*l0 + R[4]*l1 + R[5]*l2 + tv[1];
        float gz = R[6]*l0 + R[7]*l1 + R[8]*l2 + tv[2];
        kout[16 + pp*3 + 0] = gx;
        kout[16 + pp*3 + 1] = gy;
        kout[16 + pp*3 + 2] = gz;
        s2 = fmaf(gx, gx, fmaf(gy, gy, fmaf(gz, gz, s2)));
    }
    kout[28] = 1.f; kout[29] = -0.5f*hw*s2; kout[30] = 0.f; kout[31] = 0.f;
    float* pv = &g_pv[(h*LSK + j)*48];
#pragma unroll
    for (int c = 0; c < 16; c++) pv[c] = g_kv[j*384 + h*32 + 16 + c];
#pragma unroll
    for (int pp = 4; pp < 12; pp++) {
        float l0 = g_kvp_raw[j*432 +        h*12 + pp];
        float l1 = g_kvp_raw[j*432 + 144 +  h*12 + pp];
        float l2 = g_kvp_raw[j*432 + 288 +  h*12 + pp];
        pv[16 + (pp-4)*3 + 0] = R[0]*l0 + R[1]*l1 + R[2]*l2 + tv[0];
        pv[16 + (pp-4)*3 + 1] = R[3]*l0 + R[4]*l1 + R[5]*l2 + tv[1];
        pv[16 + (pp-4)*3 + 2] = R[6]*l0 + R[7]*l1 + R[8]*l2 + tv[2];
    }
#pragma unroll
    for (int c = 40; c < 48; c++) pv[c] = 0.f;
}

// ---------------- logits: 64x64 tile, dual FFMA2 accumulators ----------------
__global__ __launch_bounds__(256) void logits_kernel(
    const float* __restrict__ dst_mask, const float* __restrict__ src_mask,
    float* __restrict__ a_out, float* __restrict__ asd_out, float* __restrict__ apts_out)
{
    __shared__ float As2[32][132];   // q duplicated pairs: col = 2m
    __shared__ float Bs[32][68];
    __shared__ float dmt[64], smt[64];
    const int h  = blockIdx.z;
    const int i0 = blockIdx.y * 64;
    const int j0 = blockIdx.x * 64;
    const int t  = threadIdx.x;
    const int tx = t & 15, ty = t >> 4;

#pragma unroll
    for (int u = 0; u < 2; u++) {
        int idx = t + 256*u;
        int m = idx >> 3, c4 = idx & 7;
        float4 va = *(const float4*)&g_qaug[(h*LDQ + i0 + m)*32 + c4*4];
        float4 vb = *(const float4*)&g_kaug[(h*LSK + j0 + m)*32 + c4*4];
        As2[c4*4+0][2*m] = va.x; As2[c4*4+0][2*m+1] = va.x;
        As2[c4*4+1][2*m] = va.y; As2[c4*4+1][2*m+1] = va.y;
        As2[c4*4+2][2*m] = va.z; As2[c4*4+2][2*m+1] = va.z;
        As2[c4*4+3][2*m] = va.w; As2[c4*4+3][2*m+1] = va.w;
        Bs[c4*4+0][m] = vb.x; Bs[c4*4+1][m] = vb.y; Bs[c4*4+2][m] = vb.z; Bs[c4*4+3][m] = vb.w;
    }
    if (t < 64) { dmt[t] = dst_mask[i0 + t]; smt[t] = src_mask[j0 + t]; }
    __syncthreads();

    u64 accA[4][2] = {}, accB[4][2] = {};
#pragma unroll 4
    for (int kk = 0; kk < 16; kk++) {
        u64 a0[4], b0[2];
#pragma unroll
        for (int i = 0; i < 4; i++) a0[i] = lds_u64(&As2[kk][2*(ty*4 + i)]);
#pragma unroll
        for (int j = 0; j < 2; j++) b0[j] = lds_u64(&Bs[kk][tx*4 + 2*j]);
#pragma unroll
        for (int i = 0; i < 4; i++)
#pragma unroll
            for (int j = 0; j < 2; j++)
                FMA2(accA[i][j], a0[i], b0[j]);
    }
#pragma unroll 4
    for (int kk = 16; kk < 32; kk++) {
        u64 a0[4], b0[2];
#pragma unroll
        for (int i = 0; i < 4; i++) a0[i] = lds_u64(&As2[kk][2*(ty*4 + i)]);
#pragma unroll
        for (int j = 0; j < 2; j++) b0[j] = lds_u64(&Bs[kk][tx*4 + 2*j]);
#pragma unroll
        for (int i = 0; i < 4; i++)
#pragma unroll
            for (int j = 0; j < 2; j++)
                FMA2(accB[i][j], a0[i], b0[j]);
    }

#pragma unroll
    for (int i = 0; i < 4; i++) {
        int gi = i0 + ty*4 + i;
        float dm = dmt[ty*4 + i];
        size_t off = (size_t)(h*LDQ + gi)*LSK + j0 + tx*4;
        float4 vsd, vpt, vl;
        float la[4], lb[4];
#pragma unroll
        for (int jp = 0; jp < 2; jp++) {
            float2 va2 = unpack2(accA[i][jp]);
            float2 vb2 = unpack2(accB[i][jp]);
            la[2*jp] = va2.x; la[2*jp+1] = va2.y;
            lb[2*jp] = vb2.x; lb[2*jp+1] = vb2.y;
        }
#pragma unroll
        for (int j = 0; j < 4; j++) {
            float g = dm * smt[tx*4 + j];
            ((float*)&vsd)[j] = la[j] * g;
            ((float*)&vpt)[j] = lb[j] * g;
            ((float*)&vl)[j]  = la[j] + lb[j] + 1e9f*(g - 1.f);
        }
        __stcs((float4*)&asd_out[off],  vsd);
        __stcs((float4*)&apts_out[off], vpt);
        *(float4*)&a_out[off] = vl;
    }
}

// ---------------- softmax ----------------
__global__ __launch_bounds__(256) void softmax_kernel(float* __restrict__ a_out)
{
    const int row = blockIdx.x;
    float* p = a_out + (size_t)row * LSK;
    const int t = threadIdx.x;
    float4 v0 = ((const float4*)p)[t];
    float4 v1 = ((const float4*)p)[t + 256];

    float m = fmaxf(fmaxf(fmaxf(v0.x, v0.y), fmaxf(v0.z, v0.w)),
                    fmaxf(fmaxf(v1.x, v1.y), fmaxf(v1.z, v1.w)));
    __shared__ float red[8];
    __shared__ float bcast;
#pragma unroll
    for (int o = 16; o; o >>= 1) m = fmaxf(m, __shfl_xor_sync(0xffffffffu, m, o));
    if ((t & 31) == 0) red[t >> 5] = m;
    __syncthreads();
    if (t < 8) {
        float mm = red[t];
#pragma unroll
        for (int o = 4; o; o >>= 1) mm = fmaxf(mm, __shfl_xor_sync(0xffu, mm, o));
        if (t == 0) bcast = mm;
    }
    __syncthreads();
    m = bcast;

    v0.x = fast_exp(v0.x - m); v0.y = fast_exp(v0.y - m);
    v0.z = fast_exp(v0.z - m); v0.w = fast_exp(v0.w - m);
    v1.x = fast_exp(v1.x - m); v1.y = fast_exp(v1.y - m);
    v1.z = fast_exp(v1.z - m); v1.w = fast_exp(v1.w - m);
    float s = v0.x + v0.y + v0.z + v0.w + v1.x + v1.y + v1.z + v1.w;
#pragma unroll
    for (int o = 16; o; o >>= 1) s += __shfl_xor_sync(0xffffffffu, s, o);
    __syncthreads();
    if ((t & 31) == 0) red[t >> 5] = s;
    __syncthreads();
    if (t < 8) {
        float ss = red[t];
#pragma unroll
        for (int o = 4; o; o >>= 1) ss += __shfl_xor_sync(0xffu, ss, o);
        if (t == 0) bcast = ss;
    }
    __syncthreads();
    float inv = 1.f / bcast;
    v0.x *= inv; v0.y *= inv; v0.z *= inv; v0.w *= inv;
    v1.x *= inv; v1.y *= inv; v1.z *= inv; v1.w *= inv;
    ((float4*)p)[t]       = v0;
    ((float4*)p)[t + 256] = v1;
}

// ---------------- AV: 128i x 48d tile, 256 threads, 4x6 microtile, FFMA2 ----------------
__global__ __launch_bounds__(256) void av_kernel(const float* __restrict__ a_out)
{
    __shared__ float Ps2[32][264];   // probs duplicated pairs: col = 2i
    __shared__ float Vs[32][48];
    const int jq = blockIdx.x;
    const int i0 = blockIdx.y * 128;
    const int h  = blockIdx.z;
    const int t  = threadIdx.x;
    const int tx = t & 7;
    const int ty = t >> 3;
    const int jbase = jq * 256;

    u64 acc[4][3] = {};
    for (int jt = 0; jt < 256; jt += 32) {
#pragma unroll
        for (int u = 0; u < 4; u++) {
            int idx = t + 256*u;
            int i = idx >> 3, j4 = idx & 7;
            float4 v = *(const float4*)&a_out[(size_t)(h*LDQ + i0 + i)*LSK + jbase + jt + j4*4];
            Ps2[j4*4+0][2*i] = v.x; Ps2[j4*4+0][2*i+1] = v.x;
            Ps2[j4*4+1][2*i] = v.y; Ps2[j4*4+1][2*i+1] = v.y;
            Ps2[j4*4+2][2*i] = v.z; Ps2[j4*4+2][2*i+1] = v.z;
            Ps2[j4*4+3][2*i] = v.w; Ps2[j4*4+3][2*i+1] = v.w;
        }
#pragma unroll
        for (int u = 0; u < 2; u++) {
            int idx = t + 256*u;
            if (idx < 384) {
                int j = idx / 12, d4 = idx - j*12;
                float4 v = *(const float4*)&g_pv[(size_t)(h*LSK + jbase + jt + j)*48 + d4*4];
                *(float4*)&Vs[j][d4*4] = v;
            }
        }
        __syncthreads();
#pragma unroll 8
        for (int kk = 0; kk < 32; kk++) {
            u64 pr[4], vv[3];
#pragma unroll
            for (int i = 0; i < 4; i++) pr[i] = lds_u64(&Ps2[kk][2*(ty*4 + i)]);
#pragma unroll
            for (int d = 0; d < 3; d++) vv[d] = lds_u64(&Vs[kk][tx*6 + 2*d]);
#pragma unroll
            for (int i = 0; i < 4; i++)
#pragma unroll
                for (int d = 0; d < 3; d++)
                    FMA2(acc[i][d], pr[i], vv[d]);
        }
        __syncthreads();
    }
#pragma unroll
    for (int i = 0; i < 4; i++)
#pragma unroll
        for (int d = 0; d < 3; d++) {
            float2 v = unpack2(acc[i][d]);
            size_t base = ((size_t)(jq*NH + h)*LDQ + i0 + ty*4 + i)*48 + tx*6 + 2*d;
            g_opart[base]     = v.x;
            g_opart[base + 1] = v.y;
        }
}

// ---------------- epilogue ----------------
__global__ void epilogue_kernel(const float* __restrict__ R_dst, const float* __restrict__ t_dst)
{
    const int i = blockIdx.x;
    const int t = threadIdx.x;
    if (t < 192) {
        int h = t >> 4, c = t & 15;
        float s = 0.f;
#pragma unroll
        for (int q = 0; q < 8; q++) s += g_opart[((size_t)(q*NH + h)*LDQ + i)*48 + c];
        g_cat[i*576 + t] = s;
    } else if (t < 288) {
        int pt = t - 192;
        int h = pt >> 3, p = pt & 7;
        int d = 16 + p*3;
        float ox = 0.f, oy = 0.f, oz = 0.f;
#pragma unroll
        for (int q = 0; q < 8; q++) {
            size_t base = ((size_t)(q*NH + h)*LDQ + i)*48 + d;
            ox += g_opart[base];
            oy += g_opart[base + 1];
            oz += g_opart[base + 2];
        }
        ox -= t_dst[i*3 + 0]; oy -= t_dst[i*3 + 1]; oz -= t_dst[i*3 + 2];
        const float* R = R_dst + i*9;
        float lx = R[0]*ox + R[3]*oy + R[6]*oz;
        float ly = R[1]*ox + R[4]*oy + R[7]*oz;
        float lz = R[2]*ox + R[5]*oy + R[8]*oz;
        float nrm = sqrtf(lx*lx + ly*ly + lz*lz + 1e-8f);
        float* cat = g_cat + i*576 + 192;
        cat[        pt] = lx;
        cat[ 96 +   pt] = ly;
        cat[192 +   pt] = lz;
        cat[288 +   pt] = nrm;
    }
}

// ---------------- launch ----------------
extern "C" void kernel_launch(void* const* d_in, const int* in_sizes, int n_in,
                              void* d_out, int out_size) {
    const float* s_dst    = (const float*)d_in[0];
    const float* s_src    = (const float*)d_in[1];
    const float* R_dst    = (const float*)d_in[2];
    const float* t_dst    = (const float*)d_in[3];
    const float* R_src    = (const float*)d_in[4];
    const float* t_src    = (const float*)d_in[5];
    const float* dst_mask = (const float*)d_in[6];
    const float* src_mask = (const float*)d_in[7];
    const float* W_q      = (const float*)d_in[8];
    const float* W_kv     = (const float*)d_in[9];
    const float* W_qp     = (const float*)d_in[10];
    const float* W_kvp    = (const float*)d_in[11];
    const float* W_out    = (const float*)d_in[12];
    const float* b_out    = (const float*)d_in[13];
    const float* head_w   = (const float*)d_in[14];

    float* out      = (float*)d_out;
    float* s_upd    = out;
    float* a_out    = out + (long long)LDQ*CS;
    float* asd_out  = a_out  + (long long)NH*LDQ*LSK;
    float* apts_out = asd_out + (long long)NH*LDQ*LSK;

    proj_all<<<dim3(7, 16, 4), 128>>>(s_dst, s_src, W_q, W_qp, W_kv, W_kvp);
    augq_kernel<<<(LDQ*NH + 255)/256, 256>>>(R_dst, t_dst, head_w);
    augk_kernel<<<(LSK*NH + 255)/256, 256>>>(R_src, t_src, head_w);
    logits_kernel<<<dim3(32, 8, 12), 256>>>(dst_mask, src_mask, a_out, asd_out, apts_out);
    softmax_kernel<<<NH*LDQ, 256>>>(a_out);
    av_kernel<<<dim3(8, 4, 12), 256>>>(a_out);
    epilogue_kernel<<<LDQ, 288>>>(R_dst, t_dst);
    out_gemm<<<dim3(6, 16), 128>>>(W_out, b_out, s_upd);
}

// round 14
// speedup vs baseline: 1.4764x; 1.4764x over previous
#include <cuda_runtime.h>
#include <math.h>

#define LDQ 512
#define LSK 2048
#define CS  384
#define NH  12

// ---------------- scratch ----------------
__device__ float g_q[LDQ*192];
__device__ float g_qp_raw[LDQ*144];
__device__ float g_kv[LSK*384];
__device__ float g_kvp_raw[LSK*432];
__device__ float g_qaug[NH*LDQ*32];
__device__ float g_kaug[NH*LSK*32];
__device__ float g_pv[NH*LSK*40];
__device__ float g_opart[8*NH*LDQ*40];             // AV partials (8 j-slices)
__device__ float g_cat[LDQ*576];

// ---------------- fast exp on the FMA pipe ----------------
__device__ __forceinline__ float fast_exp(float x)
{
    x = fmaxf(x, -87.0f);
    float y  = x * 1.4426950408889634f;
    float t  = y + 12582912.0f;
    int   n  = __float_as_int(t) - 0x4B400000;
    float yi = t - 12582912.0f;
    float f  = y - yi;
    float p = 1.5403530e-4f;
    p = fmaf(p, f, 1.3333558e-3f);
    p = fmaf(p, f, 9.6181291e-3f);
    p = fmaf(p, f, 5.5504109e-2f);
    p = fmaf(p, f, 2.4022651e-1f);
    p = fmaf(p, f, 6.9314718e-1f);
    p = fmaf(p, f, 1.0f);
    return __int_as_float(__float_as_int(p) + (n << 23));
}

// ---------------- 128x64 tile GEMM, 128 threads, 8x8 microtile ----------------
__device__ __forceinline__ void gemm_128x64(
    const float* __restrict__ A, const float* __restrict__ B, float* __restrict__ C,
    int M, int N, int K)
{
    __shared__ float As[16][132];
    __shared__ float Bs[16][64];
    const int t  = threadIdx.x;
    const int tx = t & 7;
    const int ty = t >> 3;
    const int m0 = blockIdx.y * 128;
    const int n0 = blockIdx.x * 64;
    float acc[8][8] = {};

    for (int kt = 0; kt < K; kt += 16) {
#pragma unroll
        for (int u = 0; u < 16; u++) {
            int idx = t + 128*u; int m = idx >> 4, k = idx & 15;
            As[k][m] = A[(m0 + m)*K + kt + k];
        }
#pragma unroll
        for (int u = 0; u < 8; u++) {
            int idx = t + 128*u; int k = idx >> 6, n = idx & 63;
            int gn = n0 + n;
            Bs[k][n] = (gn < N) ? B[(kt + k)*N + gn] : 0.f;
        }
        __syncthreads();
#pragma unroll
        for (int kk = 0; kk < 16; kk++) {
            float a0[8], b0[8];
#pragma unroll
            for (int i = 0; i < 8; i++) a0[i] = As[kk][ty*8 + i];
#pragma unroll
            for (int j = 0; j < 8; j++) b0[j] = Bs[kk][tx*8 + j];
#pragma unroll
            for (int i = 0; i < 8; i++)
#pragma unroll
                for (int j = 0; j < 8; j++)
                    acc[i][j] = fmaf(a0[i], b0[j], acc[i][j]);
        }
        __syncthreads();
    }
#pragma unroll
    for (int i = 0; i < 8; i++) {
        int gm = m0 + ty*8 + i;
#pragma unroll
        for (int j = 0; j < 8; j++) {
            int gn = n0 + tx*8 + j;
            if (gn < N) C[gm*N + gn] = acc[i][j];
        }
    }
}

__global__ __launch_bounds__(128) void proj_all(
    const float* __restrict__ s_dst, const float* __restrict__ s_src,
    const float* __restrict__ Wq, const float* __restrict__ Wqp,
    const float* __restrict__ Wkv, const float* __restrict__ Wkvp)
{
    const float* A; const float* B; float* C; int M, N;
    switch (blockIdx.z) {
        case 0:  A = s_dst; B = Wq;   C = g_q;       M = LDQ; N = 192; break;
        case 1:  A = s_dst; B = Wqp;  C = g_qp_raw;  M = LDQ; N = 144; break;
        case 2:  A = s_src; B = Wkv;  C = g_kv;      M = LSK; N = 384; break;
        default: A = s_src; B = Wkvp; C = g_kvp_raw; M = LSK; N = 432; break;
    }
    if ((int)blockIdx.x*64 >= N || (int)blockIdx.y*128 >= M) return;
    gemm_128x64(A, B, C, M, N, CS);
}

// ---------------- out GEMM: 32x64 tile, 128 threads, 4x4 microtile ----------------
__global__ __launch_bounds__(128) void out_gemm(
    const float* __restrict__ Wout, const float* __restrict__ bout, float* __restrict__ s_upd)
{
    __shared__ float As[16][33];
    __shared__ float Bs[16][64];
    const int t  = threadIdx.x;
    const int tx = t & 15;        // 16 n-groups x 4
    const int ty = t >> 4;        // 8 m-groups x 4
    const int m0 = blockIdx.y * 32;
    const int n0 = blockIdx.x * 64;
    float acc[4][4] = {};

    for (int kt = 0; kt < 576; kt += 16) {
#pragma unroll
        for (int u = 0; u < 4; u++) {
            int idx = t + 128*u; int m = idx >> 4, k = idx & 15;
            As[k][m] = g_cat[(m0 + m)*576 + kt + k];
        }
#pragma unroll
        for (int u = 0; u < 8; u++) {
            int idx = t + 128*u; int k = idx >> 6, n = idx & 63;
            Bs[k][n] = Wout[(kt + k)*384 + n0 + n];
        }
        __syncthreads();
#pragma unroll
        for (int kk = 0; kk < 16; kk++) {
            float a0[4], b0[4];
#pragma unroll
            for (int i = 0; i < 4; i++) a0[i] = As[kk][ty*4 + i];
#pragma unroll
            for (int j = 0; j < 4; j++) b0[j] = Bs[kk][tx*4 + j];
#pragma unroll
            for (int i = 0; i < 4; i++)
#pragma unroll
                for (int j = 0; j < 4; j++)
                    acc[i][j] = fmaf(a0[i], b0[j], acc[i][j]);
        }
        __syncthreads();
    }
#pragma unroll
    for (int i = 0; i < 4; i++) {
        int gm = m0 + ty*4 + i;
#pragma unroll
        for (int j = 0; j < 4; j++) {
            int gn = n0 + tx*4 + j;
            s_upd[gm*384 + gn] = acc[i][j] + bout[gn];
        }
    }
}

// ---------------- augmentation (fused q+k in one launch) ----------------
__global__ void aug_kernel(const float* __restrict__ R_dst, const float* __restrict__ t_dst,
                           const float* __restrict__ R_src, const float* __restrict__ t_src,
                           const float* __restrict__ head_w)
{
    int idx = blockIdx.x*256 + threadIdx.x;
    if (idx < LDQ*NH) {
        int i = idx / NH, h = idx - (idx/NH)*NH;
        float hw = log1pf(__expf(head_w[h])) * (1.0f/6.0f);
        const float qksc = 0.17677669529663689f;
        float* outp = &g_qaug[(h*LDQ + i)*32];
#pragma unroll
        for (int c = 0; c < 16; c++) outp[c] = g_q[i*192 + h*16 + c] * qksc;
        const float* R = R_dst + i*9; const float* tv = t_dst + i*3;
        float s2 = 0.f;
#pragma unroll
        for (int p = 0; p < 4; p++) {
            float l0 = g_qp_raw[i*144 +       h*4 + p];
            float l1 = g_qp_raw[i*144 + 48  + h*4 + p];
            float l2 = g_qp_raw[i*144 + 96  + h*4 + p];
            float gx = R[0]*l0 + R[1]*l1 + R[2]*l2 + tv[0];
            float gy = R[3]*l0 + R[4]*l1 + R[5]*l2 + tv[1];
            float gz = R[6]*l0 + R[7]*l1 + R[8]*l2 + tv[2];
            outp[16 + p*3 + 0] = hw*gx;
            outp[16 + p*3 + 1] = hw*gy;
            outp[16 + p*3 + 2] = hw*gz;
            s2 = fmaf(gx, gx, fmaf(gy, gy, fmaf(gz, gz, s2)));
        }
        outp[28] = -0.5f*hw*s2; outp[29] = 1.f; outp[30] = 0.f; outp[31] = 0.f;
        return;
    }
    idx -= LDQ*NH;
    if (idx >= LSK*NH) return;
    int j = idx / NH, h = idx - (idx/NH)*NH;
    float hw = log1pf(__expf(head_w[h])) * (1.0f/6.0f);
    float* kout = &g_kaug[(h*LSK + j)*32];
#pragma unroll
    for (int c = 0; c < 16; c++) kout[c] = g_kv[j*384 + h*32 + c];
    const float* R = R_src + j*9; const float* tv = t_src + j*3;
    float s2 = 0.f;
#pragma unroll
    for (int pp = 0; pp < 4; pp++) {
        float l0 = g_kvp_raw[j*432 +        h*12 + pp];
        float l1 = g_kvp_raw[j*432 + 144 +  h*12 + pp];
        float l2 = g_kvp_raw[j*432 + 288 +  h*12 + pp];
        float gx = R[0]*l0 + R[1]*l1 + R[2]*l2 + tv[0];
        float gy = R[3]*l0 + R[4]*l1 + R[5]*l2 + tv[1];
        float gz = R[6]*l0 + R[7]*l1 + R[8]*l2 + tv[2];
        kout[16 + pp*3 + 0] = gx;
        kout[16 + pp*3 + 1] = gy;
        kout[16 + pp*3 + 2] = gz;
        s2 = fmaf(gx, gx, fmaf(gy, gy, fmaf(gz, gz, s2)));
    }
    kout[28] = 1.f; kout[29] = -0.5f*hw*s2; kout[30] = 0.f; kout[31] = 0.f;
    float* pv = &g_pv[(h*LSK + j)*40];
#pragma unroll
    for (int c = 0; c < 16; c++) pv[c] = g_kv[j*384 + h*32 + 16 + c];
#pragma unroll
    for (int pp = 4; pp < 12; pp++) {
        float l0 = g_kvp_raw[j*432 +        h*12 + pp];
        float l1 = g_kvp_raw[j*432 + 144 +  h*12 + pp];
        float l2 = g_kvp_raw[j*432 + 288 +  h*12 + pp];
        pv[16 + (pp-4)*3 + 0] = R[0]*l0 + R[1]*l1 + R[2]*l2 + tv[0];
        pv[16 + (pp-4)*3 + 1] = R[3]*l0 + R[4]*l1 + R[5]*l2 + tv[1];
        pv[16 + (pp-4)*3 + 2] = R[6]*l0 + R[7]*l1 + R[8]*l2 + tv[2];
    }
}

// ---------------- logits: 64x64 tile, dual accumulators; raw logits -> a_out ----------------
__global__ __launch_bounds__(256) void logits_kernel(
    const float* __restrict__ dst_mask, const float* __restrict__ src_mask,
    float* __restrict__ a_out, float* __restrict__ asd_out, float* __restrict__ apts_out)
{
    __shared__ float As[32][68];
    __shared__ float Bs[32][68];
    __shared__ float dmt[64], smt[64];
    const int h  = blockIdx.z;
    const int i0 = blockIdx.y * 64;
    const int j0 = blockIdx.x * 64;
    const int t  = threadIdx.x;
    const int tx = t & 15, ty = t >> 4;

#pragma unroll
    for (int u = 0; u < 2; u++) {
        int idx = t + 256*u;
        int m = idx >> 3, c4 = idx & 7;
        float4 va = *(const float4*)&g_qaug[(h*LDQ + i0 + m)*32 + c4*4];
        float4 vb = *(const float4*)&g_kaug[(h*LSK + j0 + m)*32 + c4*4];
        As[c4*4+0][m] = va.x; As[c4*4+1][m] = va.y; As[c4*4+2][m] = va.z; As[c4*4+3][m] = va.w;
        Bs[c4*4+0][m] = vb.x; Bs[c4*4+1][m] = vb.y; Bs[c4*4+2][m] = vb.z; Bs[c4*4+3][m] = vb.w;
    }
    if (t < 64) { dmt[t] = dst_mask[i0 + t]; smt[t] = src_mask[j0 + t]; }
    __syncthreads();

    float accA[4][4] = {}, accB[4][4] = {};
#pragma unroll 4
    for (int kk = 0; kk < 16; kk++) {
        float a0[4], b0[4];
#pragma unroll
        for (int i = 0; i < 4; i++) a0[i] = As[kk][ty*4 + i];
#pragma unroll
        for (int j = 0; j < 4; j++) b0[j] = Bs[kk][tx*4 + j];
#pragma unroll
        for (int i = 0; i < 4; i++)
#pragma unroll
            for (int j = 0; j < 4; j++)
                accA[i][j] = fmaf(a0[i], b0[j], accA[i][j]);
    }
#pragma unroll 4
    for (int kk = 16; kk < 32; kk++) {
        float a0[4], b0[4];
#pragma unroll
        for (int i = 0; i < 4; i++) a0[i] = As[kk][ty*4 + i];
#pragma unroll
        for (int j = 0; j < 4; j++) b0[j] = Bs[kk][tx*4 + j];
#pragma unroll
        for (int i = 0; i < 4; i++)
#pragma unroll
            for (int j = 0; j < 4; j++)
                accB[i][j] = fmaf(a0[i], b0[j], accB[i][j]);
    }

#pragma unroll
    for (int i = 0; i < 4; i++) {
        int gi = i0 + ty*4 + i;
        float dm = dmt[ty*4 + i];
        size_t off = (size_t)(h*LDQ + gi)*LSK + j0 + tx*4;
        float4 vsd, vpt, vl;
#pragma unroll
        for (int j = 0; j < 4; j++) {
            float g = dm * smt[tx*4 + j];
            float la = accA[i][j], lb = accB[i][j];
            ((float*)&vsd)[j] = la * g;
            ((float*)&vpt)[j] = lb * g;
            ((float*)&vl)[j]  = la + lb + 1e9f*(g - 1.f);
        }
        __stcs((float4*)&asd_out[off],  vsd);
        __stcs((float4*)&apts_out[off], vpt);
        *(float4*)&a_out[off] = vl;
    }
}

// ---------------- softmax over each (h,i) row of 2048, in-place ----------------
__global__ __launch_bounds__(256) void softmax_kernel(float* __restrict__ a_out)
{
    const int row = blockIdx.x;
    float* p = a_out + (size_t)row * LSK;
    const int t = threadIdx.x;
    float4 v0 = ((const float4*)p)[t];
    float4 v1 = ((const float4*)p)[t + 256];

    float m = fmaxf(fmaxf(fmaxf(v0.x, v0.y), fmaxf(v0.z, v0.w)),
                    fmaxf(fmaxf(v1.x, v1.y), fmaxf(v1.z, v1.w)));
    __shared__ float red[8];
    __shared__ float bcast;
#pragma unroll
    for (int o = 16; o; o >>= 1) m = fmaxf(m, __shfl_xor_sync(0xffffffffu, m, o));
    if ((t & 31) == 0) red[t >> 5] = m;
    __syncthreads();
    if (t < 8) {
        float mm = red[t];
#pragma unroll
        for (int o = 4; o; o >>= 1) mm = fmaxf(mm, __shfl_xor_sync(0xffu, mm, o));
        if (t == 0) bcast = mm;
    }
    __syncthreads();
    m = bcast;

    v0.x = fast_exp(v0.x - m); v0.y = fast_exp(v0.y - m);
    v0.z = fast_exp(v0.z - m); v0.w = fast_exp(v0.w - m);
    v1.x = fast_exp(v1.x - m); v1.y = fast_exp(v1.y - m);
    v1.z = fast_exp(v1.z - m); v1.w = fast_exp(v1.w - m);
    float s = v0.x + v0.y + v0.z + v0.w + v1.x + v1.y + v1.z + v1.w;
#pragma unroll
    for (int o = 16; o; o >>= 1) s += __shfl_xor_sync(0xffffffffu, s, o);
    __syncthreads();
    if ((t & 31) == 0) red[t >> 5] = s;
    __syncthreads();
    if (t < 8) {
        float ss = red[t];
#pragma unroll
        for (int o = 4; o; o >>= 1) ss += __shfl_xor_sync(0xffu, ss, o);
        if (t == 0) bcast = ss;
    }
    __syncthreads();
    float inv = 1.f / bcast;
    v0.x *= inv; v0.y *= inv; v0.z *= inv; v0.w *= inv;
    v1.x *= inv; v1.y *= inv; v1.z *= inv; v1.w *= inv;
    ((float4*)p)[t]       = v0;
    ((float4*)p)[t + 256] = v1;
}

// ---------------- AV: 128i x 40d tile, 256 threads, 4x5 microtile, 8-way j split ----------------
__global__ __launch_bounds__(256) void av_kernel(const float* __restrict__ a_out)
{
    __shared__ float Ps[32][132];
    __shared__ float Vs[32][40];
    const int jq = blockIdx.x;
    const int i0 = blockIdx.y * 128;
    const int h  = blockIdx.z;
    const int t  = threadIdx.x;
    const int tx = t & 7;
    const int ty = t >> 3;
    const int jbase = jq * 256;

    float acc[4][5] = {};
    for (int jt = 0; jt < 256; jt += 32) {
#pragma unroll
        for (int u = 0; u < 4; u++) {
            int idx = t + 256*u;
            int i = idx >> 3, j4 = idx & 7;
            float4 v = *(const float4*)&a_out[(size_t)(h*LDQ + i0 + i)*LSK + jbase + jt + j4*4];
            Ps[j4*4+0][i] = v.x; Ps[j4*4+1][i] = v.y; Ps[j4*4+2][i] = v.z; Ps[j4*4+3][i] = v.w;
        }
#pragma unroll
        for (int u = 0; u < 2; u++) {
            int idx = t + 256*u;
            if (idx < 320) {
                int j = idx / 10, d4 = idx - j*10;
                float4 v = *(const float4*)&g_pv[(size_t)(h*LSK + jbase + jt + j)*40 + d4*4];
                Vs[j][d4*4+0] = v.x; Vs[j][d4*4+1] = v.y; Vs[j][d4*4+2] = v.z; Vs[j][d4*4+3] = v.w;
            }
        }
        __syncthreads();
#pragma unroll 8
        for (int kk = 0; kk < 32; kk++) {
            float pr[4], vv[5];
#pragma unroll
            for (int i = 0; i < 4; i++) pr[i] = Ps[kk][ty*4 + i];
#pragma unroll
            for (int d = 0; d < 5; d++) vv[d] = Vs[kk][tx*5 + d];
#pragma unroll
            for (int i = 0; i < 4; i++)
#pragma unroll
                for (int d = 0; d < 5; d++)
                    acc[i][d] = fmaf(pr[i], vv[d], acc[i][d]);
        }
        __syncthreads();
    }
#pragma unroll
    for (int i = 0; i < 4; i++)
#pragma unroll
        for (int d = 0; d < 5; d++)
            g_opart[((size_t)(jq*NH + h)*LDQ + i0 + ty*4 + i)*40 + tx*5 + d] = acc[i][d];
}

// ---------------- epilogue: reduce 8 partials, invert frame, norms, build cat ----------------
__global__ void epilogue_kernel(const float* __restrict__ R_dst, const float* __restrict__ t_dst)
{
    const int i = blockIdx.x;
    const int t = threadIdx.x;
    if (t < 192) {
        int h = t >> 4, c = t & 15;
        float s = 0.f;
#pragma unroll
        for (int q = 0; q < 8; q++) s += g_opart[((size_t)(q*NH + h)*LDQ + i)*40 + c];
        g_cat[i*576 + t] = s;
    } else if (t < 288) {
        int pt = t - 192;
        int h = pt >> 3, p = pt & 7;
        int d = 16 + p*3;
        float ox = 0.f, oy = 0.f, oz = 0.f;
#pragma unroll
        for (int q = 0; q < 8; q++) {
            size_t base = ((size_t)(q*NH + h)*LDQ + i)*40 + d;
            ox += g_opart[base];
            oy += g_opart[base + 1];
            oz += g_opart[base + 2];
        }
        ox -= t_dst[i*3 + 0]; oy -= t_dst[i*3 + 1]; oz -= t_dst[i*3 + 2];
        const float* R = R_dst + i*9;
        float lx = R[0]*ox + R[3]*oy + R[6]*oz;
        float ly = R[1]*ox + R[4]*oy + R[7]*oz;
        float lz = R[2]*ox + R[5]*oy + R[8]*oz;
        float nrm = sqrtf(lx*lx + ly*ly + lz*lz + 1e-8f);
        float* cat = g_cat + i*576 + 192;
        cat[        pt] = lx;
        cat[ 96 +   pt] = ly;
        cat[192 +   pt] = lz;
        cat[288 +   pt] = nrm;
    }
}

// ---------------- launch ----------------
extern "C" void kernel_launch(void* const* d_in, const int* in_sizes, int n_in,
                              void* d_out, int out_size) {
    const float* s_dst    = (const float*)d_in[0];
    const float* s_src    = (const float*)d_in[1];
    const float* R_dst    = (const float*)d_in[2];
    const float* t_dst    = (const float*)d_in[3];
    const float* R_src    = (const float*)d_in[4];
    const float* t_src    = (const float*)d_in[5];
    const float* dst_mask = (const float*)d_in[6];
    const float* src_mask = (const float*)d_in[7];
    const float* W_q      = (const float*)d_in[8];
    const float* W_kv     = (const float*)d_in[9];
    const float* W_qp     = (const float*)d_in[10];
    const float* W_kvp    = (const float*)d_in[11];
    const float* W_out    = (const float*)d_in[12];
    const float* b_out    = (const float*)d_in[13];
    const float* head_w   = (const float*)d_in[14];

    float* out      = (float*)d_out;
    float* s_upd    = out;
    float* a_out    = out + (long long)LDQ*CS;
    float* asd_out  = a_out  + (long long)NH*LDQ*LSK;
    float* apts_out = asd_out + (long long)NH*LDQ*LSK;

    proj_all<<<dim3(7, 16, 4), 128>>>(s_dst, s_src, W_q, W_qp, W_kv, W_kvp);
    aug_kernel<<<((LDQ+LSK)*NH + 255)/256, 256>>>(R_dst, t_dst, R_src, t_src, head_w);
    logits_kernel<<<dim3(32, 8, 12), 256>>>(dst_mask, src_mask, a_out, asd_out, apts_out);
    softmax_kernel<<<NH*LDQ, 256>>>(a_out);
    av_kernel<<<dim3(8, 4, 12), 256>>>(a_out);
    epilogue_kernel<<<LDQ, 288>>>(R_dst, t_dst);
    out_gemm<<<dim3(6, 16), 128>>>(W_out, b_out, s_upd);
}